// round 1
// baseline (speedup 1.0000x reference)
#include <cuda_runtime.h>
#include <cuda_bf16.h>

// Problem constants
#define NVEC   32768            // 8*64*64 rows
#define DIM    256
#define NCODE  4096

// Output layout (all fp32): [quantize 8388608][diff 1][ind 32768]
#define Q_ELEMS   (NVEC * DIM)          // 8388608
#define DIFF_OFF  Q_ELEMS               // 8388608
#define IND_OFF   (Q_ELEMS + 1)         // 8388609

// Scratch (device globals: no allocation allowed)
__device__ float  g_embedT[NCODE * DIM];   // 4 MB transposed codebook
__device__ float  g_enorm[NCODE];          // ||e_j||^2
__device__ int    g_ind[NVEC];             // argmin indices
__device__ double g_part[4096];            // per-block diff partials

// ---------------------------------------------------------------------------
// ||e_j||^2 : embed is [DIM][NCODE], column j strided. Consecutive j per lane
// => fully coalesced.
__global__ void enorm_kernel(const float* __restrict__ embed) {
    int j = blockIdx.x * blockDim.x + threadIdx.x;
    float s = 0.f;
#pragma unroll 8
    for (int d = 0; d < DIM; d++) {
        float v = embed[d * NCODE + j];
        s += v * v;
    }
    g_enorm[j] = s;
}

// ---------------------------------------------------------------------------
// embedT[j][d] = embed[d][j]  (32x32 smem tile transpose)
__global__ void transpose_kernel(const float* __restrict__ embed) {
    __shared__ float tile[32][33];
    int j0 = blockIdx.x * 32;
    int d0 = blockIdx.y * 32;
    int tx = threadIdx.x, ty = threadIdx.y;   // 32 x 8
#pragma unroll
    for (int i = 0; i < 4; i++)
        tile[ty + i * 8][tx] = embed[(size_t)(d0 + ty + i * 8) * NCODE + j0 + tx];
    __syncthreads();
#pragma unroll
    for (int i = 0; i < 4; i++)
        g_embedT[(size_t)(j0 + ty + i * 8) * DIM + d0 + tx] = tile[tx][ty + i * 8];
}

// ---------------------------------------------------------------------------
// Fused distance-GEMM + argmin.
// Tile: 64 rows x 64 cols, 256 threads, 4x4 micro-tile, K chunked by 32.
// X tile [64][256] stays resident in smem for the entire 4096-column sweep.
#define TR 64
#define TC 64
#define TK 32
#define XP 257          // padded X row stride (floats)
#define EP 68           // padded E row stride (floats, mult of 4 for float4)

// dynamic smem bytes
#define ARGMIN_SMEM ((TR * XP + TK * EP + TR * 16) * 4 + TR * 16 * 4)

__global__ void argmin_kernel(const float* __restrict__ x,
                              const float* __restrict__ embed,
                              float* __restrict__ out) {
    extern __shared__ float smem[];
    float* Xs   = smem;                       // [64][257]
    float* Es   = Xs + TR * XP;               // [32][68]
    float* redV = Es + TK * EP;               // [64][16]
    int*   redI = (int*)(redV + TR * 16);     // [64][16]

    const int t  = threadIdx.x;
    const int tx = t & 15;
    const int ty = t >> 4;
    const int n0 = blockIdx.x * TR;

    // Load X tile: row r, column t. Coalesced, conflict-free writes.
#pragma unroll 4
    for (int r = 0; r < TR; r++)
        Xs[r * XP + t] = x[(size_t)(n0 + r) * DIM + t];

    float bestV[4];
    int   bestI[4];
#pragma unroll
    for (int i = 0; i < 4; i++) { bestV[i] = 3.4e38f; bestI[i] = 0; }

    for (int j0 = 0; j0 < NCODE; j0 += TC) {
        float acc[4][4];
#pragma unroll
        for (int i = 0; i < 4; i++)
#pragma unroll
            for (int jj = 0; jj < 4; jj++) acc[i][jj] = 0.f;

        for (int k0 = 0; k0 < DIM; k0 += TK) {
            __syncthreads();   // protect Es (and first iter: X tile) from reuse
            // Load Es[32][64]: 512 float4 slots, 2 per thread. Coalesced.
#pragma unroll
            for (int i = 0; i < 2; i++) {
                int s4 = t + i * 256;
                int kk = s4 >> 4;
                int c4 = (s4 & 15) * 4;
                float4 v = *(const float4*)&embed[(size_t)(k0 + kk) * NCODE + j0 + c4];
                *(float4*)&Es[kk * EP + c4] = v;
            }
            __syncthreads();

#pragma unroll
            for (int k = 0; k < TK; k++) {
                float xr[4];
#pragma unroll
                for (int i = 0; i < 4; i++)
                    xr[i] = Xs[(ty * 4 + i) * XP + k0 + k];
                float4 e4 = *(const float4*)&Es[k * EP + tx * 4];
                float er[4] = {e4.x, e4.y, e4.z, e4.w};
#pragma unroll
                for (int i = 0; i < 4; i++)
#pragma unroll
                    for (int jj = 0; jj < 4; jj++)
                        acc[i][jj] += xr[i] * er[jj];
            }
        }

        // Epilogue for this 64-column chunk: dist = ||e||^2 - 2*dot
#pragma unroll
        for (int jj = 0; jj < 4; jj++) {
            int j = j0 + tx * 4 + jj;
            float en = __ldg(&g_enorm[j]);
#pragma unroll
            for (int i = 0; i < 4; i++) {
                float dist = en - 2.0f * acc[i][jj];
                if (dist < bestV[i] || (dist == bestV[i] && j < bestI[i])) {
                    bestV[i] = dist;
                    bestI[i] = j;
                }
            }
        }
    }

    // Cross-tx reduction per row (16 candidates per row)
    __syncthreads();
#pragma unroll
    for (int i = 0; i < 4; i++) {
        redV[(ty * 4 + i) * 16 + tx] = bestV[i];
        redI[(ty * 4 + i) * 16 + tx] = bestI[i];
    }
    __syncthreads();
    if (tx == 0) {
#pragma unroll
        for (int i = 0; i < 4; i++) {
            int r = ty * 4 + i;
            float bv = redV[r * 16];
            int   bi = redI[r * 16];
            for (int u = 1; u < 16; u++) {
                float v  = redV[r * 16 + u];
                int   id = redI[r * 16 + u];
                if (v < bv || (v == bv && id < bi)) { bv = v; bi = id; }
            }
            g_ind[n0 + r] = bi;
            out[IND_OFF + n0 + r] = (float)bi;
        }
    }
}

// ---------------------------------------------------------------------------
// Gather codebook rows + fused diff partial sums. One warp per row.
__global__ void gather_kernel(const float* __restrict__ input,
                              float* __restrict__ out) {
    int wid = threadIdx.x >> 5, lane = threadIdx.x & 31;
    int n = blockIdx.x * 8 + wid;
    int ind = g_ind[n];
    const float4* e4 = (const float4*)(g_embedT + (size_t)ind * DIM);
    const float4* x4 = (const float4*)(input + (size_t)n * DIM);
    float4* o4 = (float4*)(out + (size_t)n * DIM);
    float s = 0.f;
#pragma unroll
    for (int i = 0; i < 2; i++) {
        float4 e  = e4[lane + i * 32];
        float4 xx = x4[lane + i * 32];
        o4[lane + i * 32] = e;
        float d0 = e.x - xx.x, d1 = e.y - xx.y, d2 = e.z - xx.z, d3 = e.w - xx.w;
        s += d0 * d0 + d1 * d1 + d2 * d2 + d3 * d3;
    }
    double sd = (double)s;
#pragma unroll
    for (int off = 16; off; off >>= 1)
        sd += __shfl_xor_sync(0xffffffffu, sd, off);
    __shared__ double ws[8];
    if (lane == 0) ws[wid] = sd;
    __syncthreads();
    if (threadIdx.x == 0) {
        double tot = 0.0;
#pragma unroll
        for (int i = 0; i < 8; i++) tot += ws[i];
        g_part[blockIdx.x] = tot;
    }
}

// Final deterministic reduction of 4096 partials -> diff scalar
__global__ void diff_kernel(float* __restrict__ out) {
    __shared__ double s[128];
    int t = threadIdx.x;
    double a = 0.0;
    for (int i = 0; i < 32; i++) a += g_part[t + i * 128];
    s[t] = a;
    __syncthreads();
    if (t == 0) {
        double tot = 0.0;
        for (int i = 0; i < 128; i++) tot += s[i];
        out[DIFF_OFF] = (float)(tot / (double)Q_ELEMS);
    }
}

// ---------------------------------------------------------------------------
extern "C" void kernel_launch(void* const* d_in, const int* in_sizes, int n_in,
                              void* d_out, int out_size) {
    const float* input = (const float*)d_in[0];   // [8,64,64,256]
    const float* embed = (const float*)d_in[1];   // [256,4096]
    float* out = (float*)d_out;

    enorm_kernel<<<NCODE / 256, 256>>>(embed);
    transpose_kernel<<<dim3(NCODE / 32, DIM / 32), dim3(32, 8)>>>(embed);

    cudaFuncSetAttribute(argmin_kernel,
                         cudaFuncAttributeMaxDynamicSharedMemorySize,
                         ARGMIN_SMEM);
    argmin_kernel<<<NVEC / TR, 256, ARGMIN_SMEM>>>(input, embed, out);

    gather_kernel<<<NVEC / 8, 256>>>(input, out);
    diff_kernel<<<1, 128>>>(out);
}

// round 5
// speedup vs baseline: 2.4815x; 2.4815x over previous
#include <cuda_runtime.h>
#include <cuda_fp16.h>
#include <cstdint>

// Problem constants
#define NVEC   32768
#define DIM    256
#define NCODE  4096

// Output layout (all fp32): [quantize 8388608][diff 1][ind 32768]
#define Q_ELEMS   (NVEC * DIM)
#define DIFF_OFF  Q_ELEMS
#define IND_OFF   (Q_ELEMS + 1)

// Scratch
__device__ float  g_embedT[NCODE * DIM];            // [code][dim] fp32
__device__ __align__(16) __half g_Bh[NCODE * DIM];  // [code][dim] hi halves
__device__ __align__(16) __half g_Bl[NCODE * DIM];  // [code][dim] lo halves
__device__ float  g_enorm[NCODE];
__device__ int    g_cand[NVEC * 4];                 // 4 candidates per row
__device__ double g_part[4096];

// ---------------------------------------------------------------------------
// Portable tensor-ISA helpers
// ---------------------------------------------------------------------------
__device__ __forceinline__ uint32_t smem_u32(const void* p) {
    uint32_t a;
    asm("{ .reg .u64 t; cvta.to.shared.u64 t, %1; cvt.u32.u64 %0, t; }"
        : "=r"(a) : "l"(p));
    return a;
}
__device__ __forceinline__ void ldsm_x4(uint32_t r[4], uint32_t addr) {
    asm volatile("ldmatrix.sync.aligned.m8n8.x4.shared.b16 {%0,%1,%2,%3}, [%4];"
                 : "=r"(r[0]), "=r"(r[1]), "=r"(r[2]), "=r"(r[3]) : "r"(addr));
}
__device__ __forceinline__ void mma_f16(float c[4], const uint32_t a[4],
                                        const uint32_t b0, const uint32_t b1) {
    asm volatile(
        "mma.sync.aligned.m16n8k16.row.col.f32.f16.f16.f32 "
        "{%0,%1,%2,%3}, {%4,%5,%6,%7}, {%8,%9}, {%0,%1,%2,%3};"
        : "+f"(c[0]), "+f"(c[1]), "+f"(c[2]), "+f"(c[3])
        : "r"(a[0]), "r"(a[1]), "r"(a[2]), "r"(a[3]), "r"(b0), "r"(b1));
}
#define CP_ASYNC16(dst, src) \
    asm volatile("cp.async.cg.shared.global [%0], [%1], 16;" \
                 :: "r"(dst), "l"(src) : "memory")
#define CP_COMMIT()  asm volatile("cp.async.commit_group;" ::: "memory")
#define CP_WAIT2()   asm volatile("cp.async.wait_group 2;" ::: "memory")

// ---------------------------------------------------------------------------
#define A_ROW_B   528
#define A_PLANE_B 67584            // 128*528
#define B_BASE    135168           // 2*A_PLANE_B
#define B_ROW_B   80
#define B_PLANE_B 10240            // 128*80
#define B_BUF_B   20480            // hi+lo
#define SMEM_TOT  (B_BASE + 4 * B_BUF_B)   // 217088

// ===========================================================================
// Fused split-fp16 mma GEMM + per-half top-2 argmin. Grid 256, block 256.
// ===========================================================================
__global__ __launch_bounds__(256, 1)
void vq_mma_kernel(const float* __restrict__ x) {
    extern __shared__ char smem[];
    const uint32_t sb = smem_u32(smem);
    const int t    = threadIdx.x;
    const int wid  = t >> 5, lane = t & 31;
    const int n0   = blockIdx.x * 128;
    const int mwarp = (wid & 3) * 32;
    const int nwarp = (wid >> 2) * 64;

    // ---- convert A (x rows) to hi/lo fp16 in smem -------------------------
    {
        const float4* xg4 = (const float4*)(x + (size_t)n0 * DIM);
#pragma unroll
        for (int i = 0; i < 32; i++) {
            const int f   = t + i * 256;
            const int row = f >> 6;
            const int c4  = f & 63;
            float4 v = xg4[f];
            __half hx = __float2half_rn(v.x), hy = __float2half_rn(v.y);
            __half hz = __float2half_rn(v.z), hw = __float2half_rn(v.w);
            __half lx = __float2half_rn(v.x - __half2float(hx));
            __half ly = __float2half_rn(v.y - __half2float(hy));
            __half lz = __float2half_rn(v.z - __half2float(hz));
            __half lw = __float2half_rn(v.w - __half2float(hw));
            const int off = row * A_ROW_B + c4 * 8;
            *(__half2*)(smem + off)     = __halves2half2(hx, hy);
            *(__half2*)(smem + off + 4) = __halves2half2(hz, hw);
            *(__half2*)(smem + A_PLANE_B + off)     = __halves2half2(lx, ly);
            *(__half2*)(smem + A_PLANE_B + off + 4) = __halves2half2(lz, lw);
        }
    }

    const uint32_t aBaseH = sb + (uint32_t)(mwarp + (lane & 15)) * A_ROW_B
                          + (uint32_t)(((lane >> 4) & 1) * 8) * 2;
    const uint32_t aBaseL = aBaseH + A_PLANE_B;
    const uint32_t bBase = sb + B_BASE
                         + (uint32_t)(nwarp + (lane & 7) + ((lane >> 4) & 1) * 8) * B_ROW_B
                         + (uint32_t)(((lane >> 3) & 1) * 8) * 2;

    auto issueB = [&](int ch) {
        const int nb = (ch >> 3) * 128;
        const int kb = (ch & 7) * 32;
        const uint32_t bufb = sb + B_BASE + (uint32_t)(ch & 3) * B_BUF_B;
#pragma unroll
        for (int j = 0; j < 4; j++) {
            const int s = t + j * 256;
            const int plane = s >> 9;
            const int r = (s >> 2) & 127;
            const int q = s & 3;
            const uint32_t dst = bufb + (uint32_t)plane * B_PLANE_B
                               + (uint32_t)r * B_ROW_B + (uint32_t)q * 16;
            const __half* srcp = (plane ? g_Bl : g_Bh)
                               + (size_t)(nb + r) * DIM + kb + q * 8;
            CP_ASYNC16(dst, srcp);
        }
    };

    float acc[2][8][4];
#pragma unroll
    for (int mt = 0; mt < 2; mt++)
#pragma unroll
        for (int nt = 0; nt < 8; nt++)
#pragma unroll
            for (int q = 0; q < 4; q++) acc[mt][nt][q] = 0.f;

    float b1V[4], b2V[4];
    int   b1I[4], b2I[4];
#pragma unroll
    for (int q = 0; q < 4; q++) {
        b1V[q] = 3.4e38f; b2V[q] = 3.4e38f; b1I[q] = 0; b2I[q] = 1;
    }

    issueB(0); CP_COMMIT();
    issueB(1); CP_COMMIT();
    issueB(2); CP_COMMIT();

    const float2* en2 = (const float2*)g_enorm;

    for (int i = 0; i < 256; i++) {
        CP_WAIT2();
        __syncthreads();

        if (i + 3 < 256) issueB(i + 3);
        CP_COMMIT();

        const uint32_t bufb = (uint32_t)(i & 3) * B_BUF_B;
        const uint32_t kcb  = (uint32_t)(i & 7) * 32;

#pragma unroll
        for (int kk = 0; kk < 2; kk++) {
            const uint32_t kab = (kcb + kk * 16) * 2;
            uint32_t ah[2][4], al[2][4];
#pragma unroll
            for (int mt = 0; mt < 2; mt++) {
                ldsm_x4(ah[mt], aBaseH + (uint32_t)mt * (16 * A_ROW_B) + kab);
                ldsm_x4(al[mt], aBaseL + (uint32_t)mt * (16 * A_ROW_B) + kab);
            }
            uint32_t bh[8][2], bl[8][2];
#pragma unroll
            for (int np = 0; np < 4; np++) {
                uint32_t r[4];
                ldsm_x4(r, bBase + bufb + (uint32_t)np * (16 * B_ROW_B) + (uint32_t)kk * 32);
                bh[np * 2][0] = r[0]; bh[np * 2][1] = r[1];
                bh[np * 2 + 1][0] = r[2]; bh[np * 2 + 1][1] = r[3];
                ldsm_x4(r, bBase + bufb + B_PLANE_B + (uint32_t)np * (16 * B_ROW_B) + (uint32_t)kk * 32);
                bl[np * 2][0] = r[0]; bl[np * 2][1] = r[1];
                bl[np * 2 + 1][0] = r[2]; bl[np * 2 + 1][1] = r[3];
            }
#pragma unroll
            for (int mt = 0; mt < 2; mt++)
#pragma unroll
                for (int nt = 0; nt < 8; nt++) {
                    mma_f16(acc[mt][nt], ah[mt], bh[nt][0], bh[nt][1]);
                    mma_f16(acc[mt][nt], ah[mt], bl[nt][0], bl[nt][1]);
                    mma_f16(acc[mt][nt], al[mt], bh[nt][0], bh[nt][1]);
                }
        }

        if ((i & 7) == 7) {
            const int cbase = (i >> 3) * 128;
#pragma unroll
            for (int nt = 0; nt < 8; nt++) {
                const int j0 = cbase + nwarp + nt * 8 + (lane & 3) * 2;
                const float2 en = __ldg(&en2[j0 >> 1]);
#pragma unroll
                for (int mt = 0; mt < 2; mt++) {
                    float d[4];
                    d[0] = fmaf(-2.f, acc[mt][nt][0], en.x);
                    d[1] = fmaf(-2.f, acc[mt][nt][1], en.y);
                    d[2] = fmaf(-2.f, acc[mt][nt][2], en.x);
                    d[3] = fmaf(-2.f, acc[mt][nt][3], en.y);
                    const int jj[4] = {j0, j0 + 1, j0, j0 + 1};
                    const int rs[4] = {mt * 2, mt * 2, mt * 2 + 1, mt * 2 + 1};
#pragma unroll
                    for (int u = 0; u < 4; u++) {
                        const int q = rs[u];
                        const float v = d[u];
                        if (v < b2V[q]) {
                            if (v < b1V[q]) {
                                b2V[q] = b1V[q]; b2I[q] = b1I[q];
                                b1V[q] = v;      b1I[q] = jj[u];
                            } else {
                                b2V[q] = v; b2I[q] = jj[u];
                            }
                        }
                    }
                    acc[mt][nt][0] = 0.f; acc[mt][nt][1] = 0.f;
                    acc[mt][nt][2] = 0.f; acc[mt][nt][3] = 0.f;
                }
            }
        }
    }

    // ---- cross-lane top-2 merge (lanes sharing a row: xor 1, 2) ------------
#pragma unroll
    for (int q = 0; q < 4; q++) {
#pragma unroll
        for (int off = 1; off <= 2; off <<= 1) {
            float ov1 = __shfl_xor_sync(0xffffffffu, b1V[q], off);
            int   oi1 = __shfl_xor_sync(0xffffffffu, b1I[q], off);
            float ov2 = __shfl_xor_sync(0xffffffffu, b2V[q], off);
            int   oi2 = __shfl_xor_sync(0xffffffffu, b2I[q], off);
            if (ov1 < b2V[q]) {
                if (ov1 < b1V[q]) {
                    b2V[q] = b1V[q]; b2I[q] = b1I[q];
                    b1V[q] = ov1;    b1I[q] = oi1;
                } else { b2V[q] = ov1; b2I[q] = oi1; }
            }
            if (ov2 < b2V[q]) {
                if (ov2 < b1V[q]) {
                    b2V[q] = b1V[q]; b2I[q] = b1I[q];
                    b1V[q] = ov2;    b1I[q] = oi2;
                } else { b2V[q] = ov2; b2I[q] = oi2; }
            }
        }
    }

    __syncthreads();
    float* sV1 = (float*)smem;            // [128][2]
    int*   sI1 = (int*)(smem + 1024);
    float* sV2 = (float*)(smem + 2048);
    int*   sI2 = (int*)(smem + 3072);
    if ((lane & 3) == 0) {
        const int nh = wid >> 2;
#pragma unroll
        for (int q = 0; q < 4; q++) {
            const int row = mwarp + (q >> 1) * 16 + (q & 1) * 8 + (lane >> 2);
            sV1[row * 2 + nh] = b1V[q]; sI1[row * 2 + nh] = b1I[q];
            sV2[row * 2 + nh] = b2V[q]; sI2[row * 2 + nh] = b2I[q];
        }
    }
    __syncthreads();
    if (t < 128) {
        const int n = n0 + t;
        g_cand[n * 4 + 0] = sI1[t * 2];       // half0 best
        g_cand[n * 4 + 1] = sI2[t * 2];       // half0 2nd
        g_cand[n * 4 + 2] = sI1[t * 2 + 1];   // half1 best
        g_cand[n * 4 + 3] = sI2[t * 2 + 1];   // half1 2nd
    }
}

// ===========================================================================
// Prep kernels
// ===========================================================================
__global__ void enorm_kernel(const float* __restrict__ embed) {
    int j = blockIdx.x * blockDim.x + threadIdx.x;
    float s = 0.f;
#pragma unroll 8
    for (int d = 0; d < DIM; d++) {
        float v = embed[d * NCODE + j];
        s += v * v;
    }
    g_enorm[j] = s;
}

__global__ void transpose_split_kernel(const float* __restrict__ embed) {
    __shared__ float tile[32][33];
    int j0 = blockIdx.x * 32;
    int d0 = blockIdx.y * 32;
    int tx = threadIdx.x, ty = threadIdx.y;  // 32 x 8
#pragma unroll
    for (int i = 0; i < 4; i++)
        tile[ty + i * 8][tx] = embed[(size_t)(d0 + ty + i * 8) * NCODE + j0 + tx];
    __syncthreads();
#pragma unroll
    for (int i = 0; i < 4; i++) {
        float v = tile[tx][ty + i * 8];
        size_t o = (size_t)(j0 + ty + i * 8) * DIM + d0 + tx;
        g_embedT[o] = v;
        __half h = __float2half_rn(v);
        g_Bh[o] = h;
        g_Bl[o] = __float2half_rn(v - __half2float(h));
    }
}

// ===========================================================================
// Rescore (sequential k-order fp32, replicating the round-1 arithmetic that
// matched the reference on all rows) + gather + diff. One warp per row.
// ===========================================================================
__global__ __launch_bounds__(256)
void rescore_gather_kernel(const float* __restrict__ input,
                           float* __restrict__ out) {
    __shared__ float xs[8][256];
    __shared__ float es[8][4][257];
    __shared__ double ws[8];

    const int wid = threadIdx.x >> 5, lane = threadIdx.x & 31;
    const int n = blockIdx.x * 8 + wid;

    int cand[4];
#pragma unroll
    for (int c = 0; c < 4; c++) cand[c] = g_cand[n * 4 + c];

    // coalesced loads into smem
    const float4* x4 = (const float4*)(input + (size_t)n * DIM);
    float4 v0 = x4[lane], v1 = x4[lane + 32];
    *(float4*)&xs[wid][lane * 4]        = v0;
    *(float4*)&xs[wid][128 + lane * 4]  = v1;
#pragma unroll
    for (int c = 0; c < 4; c++) {
        const float4* e4 = (const float4*)(g_embedT + (size_t)cand[c] * DIM);
        float4 a = e4[lane], b = e4[lane + 32];
        es[wid][c][lane * 4 + 0] = a.x; es[wid][c][lane * 4 + 1] = a.y;
        es[wid][c][lane * 4 + 2] = a.z; es[wid][c][lane * 4 + 3] = a.w;
        es[wid][c][128 + lane * 4 + 0] = b.x; es[wid][c][128 + lane * 4 + 1] = b.y;
        es[wid][c][128 + lane * 4 + 2] = b.z; es[wid][c][128 + lane * 4 + 3] = b.w;
    }
    __syncwarp();

    // lanes 0..3: sequential k-ordered fp32 dot (round-1 rounding order)
    float dist = 3.4e38f;
    int   cidx = 0x7fffffff;
    if (lane < 4) {
        float dot = 0.f;
#pragma unroll 8
        for (int k = 0; k < 256; k++)
            dot += xs[wid][k] * es[wid][lane][k];
        float en = __ldg(&g_enorm[cand[lane]]);
        dist = en - 2.0f * dot;
        cidx = cand[lane];
    }
    // pick winner (min dist, tie -> min index)
    int slot = lane;
#pragma unroll
    for (int off = 1; off <= 2; off <<= 1) {
        float ov = __shfl_xor_sync(0xffffffffu, dist, off);
        int   oi = __shfl_xor_sync(0xffffffffu, cidx, off);
        int   os = __shfl_xor_sync(0xffffffffu, slot, off);
        if (ov < dist || (ov == dist && oi < cidx)) {
            dist = ov; cidx = oi; slot = os;
        }
    }
    const int w    = __shfl_sync(0xffffffffu, slot, 0);
    const int widx = __shfl_sync(0xffffffffu, cidx, 0);

    // gather winner row + diff partial
    float4 oa, ob;
    oa.x = es[wid][w][lane * 4 + 0]; oa.y = es[wid][w][lane * 4 + 1];
    oa.z = es[wid][w][lane * 4 + 2]; oa.w = es[wid][w][lane * 4 + 3];
    ob.x = es[wid][w][128 + lane * 4 + 0]; ob.y = es[wid][w][128 + lane * 4 + 1];
    ob.z = es[wid][w][128 + lane * 4 + 2]; ob.w = es[wid][w][128 + lane * 4 + 3];

    float4* o4 = (float4*)(out + (size_t)n * DIM);
    o4[lane]      = oa;
    o4[lane + 32] = ob;
    if (lane == 0)
        out[IND_OFF + n] = (float)widx;

    float dx0 = oa.x - v0.x, dx1 = oa.y - v0.y, dx2 = oa.z - v0.z, dx3 = oa.w - v0.w;
    float dy0 = ob.x - v1.x, dy1 = ob.y - v1.y, dy2 = ob.z - v1.z, dy3 = ob.w - v1.w;
    float s = dx0 * dx0 + dx1 * dx1 + dx2 * dx2 + dx3 * dx3
            + dy0 * dy0 + dy1 * dy1 + dy2 * dy2 + dy3 * dy3;
    double sd = (double)s;
#pragma unroll
    for (int off = 16; off; off >>= 1)
        sd += __shfl_xor_sync(0xffffffffu, sd, off);
    if (lane == 0) ws[wid] = sd;
    __syncthreads();
    if (threadIdx.x == 0) {
        double tot = 0.0;
#pragma unroll
        for (int i = 0; i < 8; i++) tot += ws[i];
        g_part[blockIdx.x] = tot;
    }
}

__global__ void diff_kernel(float* __restrict__ out) {
    __shared__ double s[128];
    int t = threadIdx.x;
    double a = 0.0;
    for (int i = 0; i < 32; i++) a += g_part[t + i * 128];
    s[t] = a;
    __syncthreads();
    if (t == 0) {
        double tot = 0.0;
        for (int i = 0; i < 128; i++) tot += s[i];
        out[DIFF_OFF] = (float)(tot / (double)Q_ELEMS);
    }
}

// ===========================================================================
extern "C" void kernel_launch(void* const* d_in, const int* in_sizes, int n_in,
                              void* d_out, int out_size) {
    const float* input = (const float*)d_in[0];   // [8,64,64,256]
    const float* embed = (const float*)d_in[1];   // [256,4096]
    float* out = (float*)d_out;

    enorm_kernel<<<NCODE / 256, 256>>>(embed);
    transpose_split_kernel<<<dim3(NCODE / 32, DIM / 32), dim3(32, 8)>>>(embed);

    cudaFuncSetAttribute(vq_mma_kernel,
                         cudaFuncAttributeMaxDynamicSharedMemorySize, SMEM_TOT);
    vq_mma_kernel<<<NVEC / 128, 256, SMEM_TOT>>>(input);

    rescore_gather_kernel<<<NVEC / 8, 256>>>(input, out);
    diff_kernel<<<1, 128>>>(out);
}

// round 6
// speedup vs baseline: 2.9866x; 1.2035x over previous
#include <cuda_runtime.h>
#include <cuda_fp16.h>
#include <cstdint>

// Problem constants
#define NVEC   32768
#define DIM    256
#define NCODE  4096

// Output layout (all fp32): [quantize 8388608][diff 1][ind 32768]
#define Q_ELEMS   (NVEC * DIM)
#define DIFF_OFF  Q_ELEMS
#define IND_OFF   (Q_ELEMS + 1)

#define NCAND  6

// Scratch
__device__ float  g_embedT[NCODE * DIM];            // [code][dim] fp32
__device__ __align__(16) __half g_Bh[NCODE * DIM];  // [code][dim] fp16 codes
__device__ float  g_enorm[NCODE];
__device__ int    g_cand[NVEC * NCAND];
__device__ double g_part[8192];

// ---------------------------------------------------------------------------
__device__ __forceinline__ uint32_t smem_u32(const void* p) {
    uint32_t a;
    asm("{ .reg .u64 t; cvta.to.shared.u64 t, %1; cvt.u32.u64 %0, t; }"
        : "=r"(a) : "l"(p));
    return a;
}
__device__ __forceinline__ void ldsm_x4(uint32_t r[4], uint32_t addr) {
    asm volatile("ldmatrix.sync.aligned.m8n8.x4.shared.b16 {%0,%1,%2,%3}, [%4];"
                 : "=r"(r[0]), "=r"(r[1]), "=r"(r[2]), "=r"(r[3]) : "r"(addr));
}
__device__ __forceinline__ void mma_f16(float c[4], const uint32_t a[4],
                                        const uint32_t b0, const uint32_t b1) {
    asm volatile(
        "mma.sync.aligned.m16n8k16.row.col.f32.f16.f16.f32 "
        "{%0,%1,%2,%3}, {%4,%5,%6,%7}, {%8,%9}, {%0,%1,%2,%3};"
        : "+f"(c[0]), "+f"(c[1]), "+f"(c[2]), "+f"(c[3])
        : "r"(a[0]), "r"(a[1]), "r"(a[2]), "r"(a[3]), "r"(b0), "r"(b1));
}
#define CP_ASYNC16(dst, src) \
    asm volatile("cp.async.cg.shared.global [%0], [%1], 16;" \
                 :: "r"(dst), "l"(src) : "memory")
#define CP_COMMIT()  asm volatile("cp.async.commit_group;" ::: "memory")
#define CP_WAIT2()   asm volatile("cp.async.wait_group 2;" ::: "memory")

// ---------------------------------------------------------------------------
// SMEM: A hi/lo resident (128 x 264 halves, 528B rows); B: 4 bufs of
// 128 rows x 40 halves (80B rows), hi plane only.
#define A_ROW_B   528
#define A_PLANE_B 67584            // 128*528
#define B_BASE    135168           // 2*A_PLANE_B
#define B_ROW_B   80
#define B_BUF_B   10240            // 128*80 (single plane)
#define SMEM_TOT  (B_BASE + 4 * B_BUF_B)   // 176128

// ===========================================================================
// 2-product split-fp16 mma GEMM + per-thread top-3 + merged top-6.
// Grid 256, block 256.
// ===========================================================================
__global__ __launch_bounds__(256, 1)
void vq_mma_kernel(const float* __restrict__ x) {
    extern __shared__ char smem[];
    const uint32_t sb = smem_u32(smem);
    const int t    = threadIdx.x;
    const int wid  = t >> 5, lane = t & 31;
    const int n0   = blockIdx.x * 128;
    const int mwarp = (wid & 3) * 32;
    const int nwarp = (wid >> 2) * 64;

    // ---- convert A (x rows) to hi/lo fp16 in smem -------------------------
    {
        const float4* xg4 = (const float4*)(x + (size_t)n0 * DIM);
#pragma unroll
        for (int i = 0; i < 32; i++) {
            const int f   = t + i * 256;
            const int row = f >> 6;
            const int c4  = f & 63;
            float4 v = xg4[f];
            __half hx = __float2half_rn(v.x), hy = __float2half_rn(v.y);
            __half hz = __float2half_rn(v.z), hw = __float2half_rn(v.w);
            __half lx = __float2half_rn(v.x - __half2float(hx));
            __half ly = __float2half_rn(v.y - __half2float(hy));
            __half lz = __float2half_rn(v.z - __half2float(hz));
            __half lw = __float2half_rn(v.w - __half2float(hw));
            const int off = row * A_ROW_B + c4 * 8;
            *(__half2*)(smem + off)     = __halves2half2(hx, hy);
            *(__half2*)(smem + off + 4) = __halves2half2(hz, hw);
            *(__half2*)(smem + A_PLANE_B + off)     = __halves2half2(lx, ly);
            *(__half2*)(smem + A_PLANE_B + off + 4) = __halves2half2(lz, lw);
        }
    }

    const uint32_t aBaseH = sb + (uint32_t)(mwarp + (lane & 15)) * A_ROW_B
                          + (uint32_t)(((lane >> 4) & 1) * 8) * 2;
    const uint32_t aBaseL = aBaseH + A_PLANE_B;
    const uint32_t bBase = sb + B_BASE
                         + (uint32_t)(nwarp + (lane & 7) + ((lane >> 4) & 1) * 8) * B_ROW_B
                         + (uint32_t)(((lane >> 3) & 1) * 8) * 2;

    // B chunk (128 codes x 32 k, fp16 hi only, 8KB): 512 x 16B
    auto issueB = [&](int ch) {
        const int nb = (ch >> 3) * 128;
        const int kb = (ch & 7) * 32;
        const uint32_t bufb = sb + B_BASE + (uint32_t)(ch & 3) * B_BUF_B;
#pragma unroll
        for (int j = 0; j < 2; j++) {
            const int s = t + j * 256;           // 0..511
            const int r = s >> 2;
            const int q = s & 3;
            const uint32_t dst = bufb + (uint32_t)r * B_ROW_B + (uint32_t)q * 16;
            const __half* srcp = g_Bh + (size_t)(nb + r) * DIM + kb + q * 8;
            CP_ASYNC16(dst, srcp);
        }
    };

    float acc[2][8][4];
#pragma unroll
    for (int mt = 0; mt < 2; mt++)
#pragma unroll
        for (int nt = 0; nt < 8; nt++)
#pragma unroll
            for (int q = 0; q < 4; q++) acc[mt][nt][q] = 0.f;

    // per-thread top-3 per row-slot (4 slots)
    float t3v[4][3];
    int   t3i[4][3];
#pragma unroll
    for (int q = 0; q < 4; q++) {
        t3v[q][0] = 3.4e38f; t3v[q][1] = 3.4e38f; t3v[q][2] = 3.4e38f;
        t3i[q][0] = 0; t3i[q][1] = 1; t3i[q][2] = 2;
    }

    issueB(0); CP_COMMIT();
    issueB(1); CP_COMMIT();
    issueB(2); CP_COMMIT();

    const float2* en2 = (const float2*)g_enorm;

    for (int i = 0; i < 256; i++) {
        CP_WAIT2();
        __syncthreads();

        if (i + 3 < 256) issueB(i + 3);
        CP_COMMIT();

        const uint32_t bufb = (uint32_t)(i & 3) * B_BUF_B;
        const uint32_t kcb  = (uint32_t)(i & 7) * 32;

#pragma unroll
        for (int kk = 0; kk < 2; kk++) {
            const uint32_t kab = (kcb + kk * 16) * 2;
            uint32_t ah[2][4], al[2][4];
#pragma unroll
            for (int mt = 0; mt < 2; mt++) {
                ldsm_x4(ah[mt], aBaseH + (uint32_t)mt * (16 * A_ROW_B) + kab);
                ldsm_x4(al[mt], aBaseL + (uint32_t)mt * (16 * A_ROW_B) + kab);
            }
            uint32_t bh[8][2];
#pragma unroll
            for (int np = 0; np < 4; np++) {
                uint32_t r[4];
                ldsm_x4(r, bBase + bufb + (uint32_t)np * (16 * B_ROW_B) + (uint32_t)kk * 32);
                bh[np * 2][0] = r[0]; bh[np * 2][1] = r[1];
                bh[np * 2 + 1][0] = r[2]; bh[np * 2 + 1][1] = r[3];
            }
#pragma unroll
            for (int mt = 0; mt < 2; mt++)
#pragma unroll
                for (int nt = 0; nt < 8; nt++) {
                    mma_f16(acc[mt][nt], ah[mt], bh[nt][0], bh[nt][1]);
                    mma_f16(acc[mt][nt], al[mt], bh[nt][0], bh[nt][1]);
                }
        }

        if ((i & 7) == 7) {
            const int cbase = (i >> 3) * 128;
#pragma unroll
            for (int nt = 0; nt < 8; nt++) {
                const int j0 = cbase + nwarp + nt * 8 + (lane & 3) * 2;
                const float2 en = __ldg(&en2[j0 >> 1]);
#pragma unroll
                for (int mt = 0; mt < 2; mt++) {
                    float d[4];
                    d[0] = fmaf(-2.f, acc[mt][nt][0], en.x);
                    d[1] = fmaf(-2.f, acc[mt][nt][1], en.y);
                    d[2] = fmaf(-2.f, acc[mt][nt][2], en.x);
                    d[3] = fmaf(-2.f, acc[mt][nt][3], en.y);
                    const int jj[4] = {j0, j0 + 1, j0, j0 + 1};
                    const int rs[4] = {mt * 2, mt * 2, mt * 2 + 1, mt * 2 + 1};
#pragma unroll
                    for (int u = 0; u < 4; u++) {
                        const int q = rs[u];
                        const float v = d[u];
                        if (v < t3v[q][2]) {
                            if (v < t3v[q][1]) {
                                t3v[q][2] = t3v[q][1]; t3i[q][2] = t3i[q][1];
                                if (v < t3v[q][0]) {
                                    t3v[q][1] = t3v[q][0]; t3i[q][1] = t3i[q][0];
                                    t3v[q][0] = v;         t3i[q][0] = jj[u];
                                } else {
                                    t3v[q][1] = v; t3i[q][1] = jj[u];
                                }
                            } else {
                                t3v[q][2] = v; t3i[q][2] = jj[u];
                            }
                        }
                    }
                    acc[mt][nt][0] = 0.f; acc[mt][nt][1] = 0.f;
                    acc[mt][nt][2] = 0.f; acc[mt][nt][3] = 0.f;
                }
            }
        }
    }

    // ---- merge: dump per-(lane-group, half) top-3 to smem, pick top-6 ------
    __syncthreads();              // all mma/ldmatrix smem reads done
    float* sV = (float*)smem;                 // [128 rows][8 src][3]
    int*   sI = (int*)(smem + 128 * 8 * 3 * 4);
    const int src = (wid >> 2) * 4 + (lane & 3);
#pragma unroll
    for (int q = 0; q < 4; q++) {
        const int row = mwarp + (q >> 1) * 16 + (q & 1) * 8 + (lane >> 2);
        const int base = (row * 8 + src) * 3;
#pragma unroll
        for (int e = 0; e < 3; e++) {
            sV[base + e] = t3v[q][e];
            sI[base + e] = t3i[q][e];
        }
    }
    __syncthreads();
    if (t < 128) {
        float v6[NCAND];
        int   i6[NCAND];
#pragma unroll
        for (int c = 0; c < NCAND; c++) { v6[c] = 3.4e38f; i6[c] = c; }
        const int base = t * 24;
        for (int e = 0; e < 24; e++) {
            float v = sV[base + e];
            int   id = sI[base + e];
            if (v < v6[NCAND - 1]) {
                int p = NCAND - 1;
                while (p > 0 && v < v6[p - 1]) {
                    v6[p] = v6[p - 1]; i6[p] = i6[p - 1]; p--;
                }
                v6[p] = v; i6[p] = id;
            }
        }
        const int n = n0 + t;
#pragma unroll
        for (int c = 0; c < NCAND; c++) g_cand[n * NCAND + c] = i6[c];
    }
}

// ===========================================================================
// Prep kernels
// ===========================================================================
__global__ void enorm_kernel(const float* __restrict__ embed) {
    int j = blockIdx.x * blockDim.x + threadIdx.x;
    float s = 0.f;
#pragma unroll 8
    for (int d = 0; d < DIM; d++) {
        float v = embed[d * NCODE + j];
        s += v * v;
    }
    g_enorm[j] = s;
}

__global__ void transpose_split_kernel(const float* __restrict__ embed) {
    __shared__ float tile[32][33];
    int j0 = blockIdx.x * 32;
    int d0 = blockIdx.y * 32;
    int tx = threadIdx.x, ty = threadIdx.y;  // 32 x 8
#pragma unroll
    for (int i = 0; i < 4; i++)
        tile[ty + i * 8][tx] = embed[(size_t)(d0 + ty + i * 8) * NCODE + j0 + tx];
    __syncthreads();
#pragma unroll
    for (int i = 0; i < 4; i++) {
        float v = tile[tx][ty + i * 8];
        size_t o = (size_t)(j0 + ty + i * 8) * DIM + d0 + tx;
        g_embedT[o] = v;
        g_Bh[o] = __float2half_rn(v);
    }
}

// ===========================================================================
// Exact rescore (sequential k-order fp32 — validated rounding order) over 6
// candidates + gather + diff. One warp per row, 4 warps per block.
// ===========================================================================
__global__ __launch_bounds__(128)
void rescore_gather_kernel(const float* __restrict__ input,
                           float* __restrict__ out) {
    __shared__ float xs[4][256];
    __shared__ float es[4][NCAND][257];
    __shared__ double ws[4];

    const int wid = threadIdx.x >> 5, lane = threadIdx.x & 31;
    const int n = blockIdx.x * 4 + wid;

    int cand[NCAND];
#pragma unroll
    for (int c = 0; c < NCAND; c++) cand[c] = g_cand[n * NCAND + c];

    const float4* x4 = (const float4*)(input + (size_t)n * DIM);
    float4 v0 = x4[lane], v1 = x4[lane + 32];
    *(float4*)&xs[wid][lane * 4]       = v0;
    *(float4*)&xs[wid][128 + lane * 4] = v1;
#pragma unroll
    for (int c = 0; c < NCAND; c++) {
        const float4* e4 = (const float4*)(g_embedT + (size_t)cand[c] * DIM);
        float4 a = e4[lane], b = e4[lane + 32];
        es[wid][c][lane * 4 + 0] = a.x; es[wid][c][lane * 4 + 1] = a.y;
        es[wid][c][lane * 4 + 2] = a.z; es[wid][c][lane * 4 + 3] = a.w;
        es[wid][c][128 + lane * 4 + 0] = b.x; es[wid][c][128 + lane * 4 + 1] = b.y;
        es[wid][c][128 + lane * 4 + 2] = b.z; es[wid][c][128 + lane * 4 + 3] = b.w;
    }
    __syncwarp();

    float dist = 3.4e38f;
    int   cidx = 0x7fffffff;
    if (lane < NCAND) {
        float dot = 0.f;
#pragma unroll 8
        for (int k = 0; k < 256; k++)
            dot += xs[wid][k] * es[wid][lane][k];
        float en = __ldg(&g_enorm[cand[lane]]);
        dist = en - 2.0f * dot;
        cidx = cand[lane];
    }
    // argmin over NCAND lanes (min dist, tie -> min index)
    float bv = dist; int bi = cidx; int bslot = lane;
#pragma unroll
    for (int l = 0; l < NCAND; l++) {
        float ov = __shfl_sync(0xffffffffu, dist, l);
        int   oi = __shfl_sync(0xffffffffu, cidx, l);
        if (ov < bv || (ov == bv && oi < bi)) { bv = ov; bi = oi; bslot = l; }
    }
    // lane-0's result is authoritative; broadcast
    const int w    = __shfl_sync(0xffffffffu, bslot, 0);
    const int widx = __shfl_sync(0xffffffffu, bi, 0);

    float4 oa, ob;
    oa.x = es[wid][w][lane * 4 + 0]; oa.y = es[wid][w][lane * 4 + 1];
    oa.z = es[wid][w][lane * 4 + 2]; oa.w = es[wid][w][lane * 4 + 3];
    ob.x = es[wid][w][128 + lane * 4 + 0]; ob.y = es[wid][w][128 + lane * 4 + 1];
    ob.z = es[wid][w][128 + lane * 4 + 2]; ob.w = es[wid][w][128 + lane * 4 + 3];

    float4* o4 = (float4*)(out + (size_t)n * DIM);
    o4[lane]      = oa;
    o4[lane + 32] = ob;
    if (lane == 0)
        out[IND_OFF + n] = (float)widx;

    float dx0 = oa.x - v0.x, dx1 = oa.y - v0.y, dx2 = oa.z - v0.z, dx3 = oa.w - v0.w;
    float dy0 = ob.x - v1.x, dy1 = ob.y - v1.y, dy2 = ob.z - v1.z, dy3 = ob.w - v1.w;
    float s = dx0 * dx0 + dx1 * dx1 + dx2 * dx2 + dx3 * dx3
            + dy0 * dy0 + dy1 * dy1 + dy2 * dy2 + dy3 * dy3;
    double sd = (double)s;
#pragma unroll
    for (int off = 16; off; off >>= 1)
        sd += __shfl_xor_sync(0xffffffffu, sd, off);
    if (lane == 0) ws[wid] = sd;
    __syncthreads();
    if (threadIdx.x == 0) {
        double tot = 0.0;
#pragma unroll
        for (int i = 0; i < 4; i++) tot += ws[i];
        g_part[blockIdx.x] = tot;
    }
}

__global__ void diff_kernel(float* __restrict__ out) {
    __shared__ double s[128];
    int t = threadIdx.x;
    double a = 0.0;
    for (int i = 0; i < 64; i++) a += g_part[t + i * 128];
    s[t] = a;
    __syncthreads();
    if (t == 0) {
        double tot = 0.0;
        for (int i = 0; i < 128; i++) tot += s[i];
        out[DIFF_OFF] = (float)(tot / (double)Q_ELEMS);
    }
}

// ===========================================================================
extern "C" void kernel_launch(void* const* d_in, const int* in_sizes, int n_in,
                              void* d_out, int out_size) {
    const float* input = (const float*)d_in[0];   // [8,64,64,256]
    const float* embed = (const float*)d_in[1];   // [256,4096]
    float* out = (float*)d_out;

    enorm_kernel<<<NCODE / 256, 256>>>(embed);
    transpose_split_kernel<<<dim3(NCODE / 32, DIM / 32), dim3(32, 8)>>>(embed);

    cudaFuncSetAttribute(vq_mma_kernel,
                         cudaFuncAttributeMaxDynamicSharedMemorySize, SMEM_TOT);
    vq_mma_kernel<<<NVEC / 128, 256, SMEM_TOT>>>(input);

    rescore_gather_kernel<<<NVEC / 4, 128>>>(input, out);
    diff_kernel<<<1, 128>>>(out);
}

// round 7
// speedup vs baseline: 3.7277x; 1.2481x over previous
#include <cuda_runtime.h>
#include <cuda_fp16.h>
#include <cstdint>

// Problem constants
#define NVEC   32768
#define DIM    256
#define NCODE  4096

// Output layout (all fp32): [quantize 8388608][diff 1][ind 32768]
#define Q_ELEMS   (NVEC * DIM)
#define DIFF_OFF  Q_ELEMS
#define IND_OFF   (Q_ELEMS + 1)

#define NCAND  6
#define MTILE  64

// Scratch
__device__ float  g_embedT[NCODE * DIM];            // [code][dim] fp32
__device__ __align__(16) __half g_Bh[NCODE * DIM];  // [code][dim] fp16 codes
__device__ float  g_enorm[NCODE];
__device__ int    g_cand[NVEC * NCAND];
__device__ double g_part[8192];

// ---------------------------------------------------------------------------
__device__ __forceinline__ uint32_t smem_u32(const void* p) {
    uint32_t a;
    asm("{ .reg .u64 t; cvta.to.shared.u64 t, %1; cvt.u32.u64 %0, t; }"
        : "=r"(a) : "l"(p));
    return a;
}
__device__ __forceinline__ void ldsm_x4(uint32_t r[4], uint32_t addr) {
    asm volatile("ldmatrix.sync.aligned.m8n8.x4.shared.b16 {%0,%1,%2,%3}, [%4];"
                 : "=r"(r[0]), "=r"(r[1]), "=r"(r[2]), "=r"(r[3]) : "r"(addr));
}
__device__ __forceinline__ void mma_f16(float c[4], const uint32_t a[4],
                                        const uint32_t b0, const uint32_t b1) {
    asm volatile(
        "mma.sync.aligned.m16n8k16.row.col.f32.f16.f16.f32 "
        "{%0,%1,%2,%3}, {%4,%5,%6,%7}, {%8,%9}, {%0,%1,%2,%3};"
        : "+f"(c[0]), "+f"(c[1]), "+f"(c[2]), "+f"(c[3])
        : "r"(a[0]), "r"(a[1]), "r"(a[2]), "r"(a[3]), "r"(b0), "r"(b1));
}
#define CP_ASYNC16(dst, src) \
    asm volatile("cp.async.cg.shared.global [%0], [%1], 16;" \
                 :: "r"(dst), "l"(src) : "memory")
#define CP_COMMIT()  asm volatile("cp.async.commit_group;" ::: "memory")
#define CP_WAIT2()   asm volatile("cp.async.wait_group 2;" ::: "memory")

// ---------------------------------------------------------------------------
// SMEM: A hi/lo resident (64 x 264 halves, 528B rows); B: 4 bufs of
// 128 codes x 32 k fp16 (80B rows).
#define A_ROW_B   528
#define A_PLANE_B 33792            // 64*528
#define B_BASE    67584            // 2*A_PLANE_B
#define B_ROW_B   80
#define B_BUF_B   10240            // 128*80
#define SMEM_TOT  (B_BASE + 4 * B_BUF_B)   // 108544 -> 2 CTAs/SM

// ===========================================================================
// 2-product split-fp16 mma GEMM + per-thread top-3 + merged top-6.
// Grid 512 (64 rows/CTA), block 256 (8 warps: 4m x 2n, warp tile 16x64).
// ===========================================================================
__global__ __launch_bounds__(256, 2)
void vq_mma_kernel(const float* __restrict__ x) {
    extern __shared__ char smem[];
    const uint32_t sb = smem_u32(smem);
    const int t    = threadIdx.x;
    const int wid  = t >> 5, lane = t & 31;
    const int n0   = blockIdx.x * MTILE;
    const int mwarp = (wid & 3) * 16;
    const int nwarp = (wid >> 2) * 64;

    // ---- convert A (64 x rows) to hi/lo fp16 in smem ----------------------
    {
        const float4* xg4 = (const float4*)(x + (size_t)n0 * DIM);
#pragma unroll
        for (int i = 0; i < 16; i++) {
            const int f   = t + i * 256;          // 0..4095 float4
            const int row = f >> 6;
            const int c4  = f & 63;
            float4 v = xg4[f];
            __half hx = __float2half_rn(v.x), hy = __float2half_rn(v.y);
            __half hz = __float2half_rn(v.z), hw = __float2half_rn(v.w);
            __half lx = __float2half_rn(v.x - __half2float(hx));
            __half ly = __float2half_rn(v.y - __half2float(hy));
            __half lz = __float2half_rn(v.z - __half2float(hz));
            __half lw = __float2half_rn(v.w - __half2float(hw));
            const int off = row * A_ROW_B + c4 * 8;
            *(__half2*)(smem + off)     = __halves2half2(hx, hy);
            *(__half2*)(smem + off + 4) = __halves2half2(hz, hw);
            *(__half2*)(smem + A_PLANE_B + off)     = __halves2half2(lx, ly);
            *(__half2*)(smem + A_PLANE_B + off + 4) = __halves2half2(lz, lw);
        }
    }

    const uint32_t aBaseH = sb + (uint32_t)(mwarp + (lane & 15)) * A_ROW_B
                          + (uint32_t)(((lane >> 4) & 1) * 8) * 2;
    const uint32_t aBaseL = aBaseH + A_PLANE_B;
    const uint32_t bBase = sb + B_BASE
                         + (uint32_t)(nwarp + (lane & 7) + ((lane >> 4) & 1) * 8) * B_ROW_B
                         + (uint32_t)(((lane >> 3) & 1) * 8) * 2;

    // B chunk (128 codes x 32 k fp16, 8KB): 512 x 16B
    auto issueB = [&](int ch) {
        const int nb = (ch >> 3) * 128;
        const int kb = (ch & 7) * 32;
        const uint32_t bufb = sb + B_BASE + (uint32_t)(ch & 3) * B_BUF_B;
#pragma unroll
        for (int j = 0; j < 2; j++) {
            const int s = t + j * 256;           // 0..511
            const int r = s >> 2;
            const int q = s & 3;
            const uint32_t dst = bufb + (uint32_t)r * B_ROW_B + (uint32_t)q * 16;
            const __half* srcp = g_Bh + (size_t)(nb + r) * DIM + kb + q * 8;
            CP_ASYNC16(dst, srcp);
        }
    };

    float acc[8][4];
#pragma unroll
    for (int nt = 0; nt < 8; nt++)
#pragma unroll
        for (int q = 0; q < 4; q++) acc[nt][q] = 0.f;

    // per-thread top-3 per row-slot (2 slots: rows lane>>2 and +8)
    float t3v[2][3];
    int   t3i[2][3];
#pragma unroll
    for (int q = 0; q < 2; q++) {
        t3v[q][0] = 3.4e38f; t3v[q][1] = 3.4e38f; t3v[q][2] = 3.4e38f;
        t3i[q][0] = 0; t3i[q][1] = 1; t3i[q][2] = 2;
    }

    issueB(0); CP_COMMIT();
    issueB(1); CP_COMMIT();
    issueB(2); CP_COMMIT();

    const float2* en2 = (const float2*)g_enorm;

    for (int i = 0; i < 256; i++) {
        CP_WAIT2();
        __syncthreads();

        if (i + 3 < 256) issueB(i + 3);
        CP_COMMIT();

        const uint32_t bufb = (uint32_t)(i & 3) * B_BUF_B;
        const uint32_t kcb  = (uint32_t)(i & 7) * 32;

#pragma unroll
        for (int kk = 0; kk < 2; kk++) {
            const uint32_t kab = (kcb + kk * 16) * 2;
            uint32_t ah[4], al[4];
            ldsm_x4(ah, aBaseH + kab);
            ldsm_x4(al, aBaseL + kab);
            uint32_t bh[8][2];
#pragma unroll
            for (int np = 0; np < 4; np++) {
                uint32_t r[4];
                ldsm_x4(r, bBase + bufb + (uint32_t)np * (16 * B_ROW_B) + (uint32_t)kk * 32);
                bh[np * 2][0] = r[0]; bh[np * 2][1] = r[1];
                bh[np * 2 + 1][0] = r[2]; bh[np * 2 + 1][1] = r[3];
            }
#pragma unroll
            for (int nt = 0; nt < 8; nt++) {
                mma_f16(acc[nt], ah, bh[nt][0], bh[nt][1]);
                mma_f16(acc[nt], al, bh[nt][0], bh[nt][1]);
            }
        }

        if ((i & 7) == 7) {
            const int cbase = (i >> 3) * 128;
#pragma unroll
            for (int nt = 0; nt < 8; nt++) {
                const int j0 = cbase + nwarp + nt * 8 + (lane & 3) * 2;
                const float2 en = __ldg(&en2[j0 >> 1]);
                float d[4];
                d[0] = fmaf(-2.f, acc[nt][0], en.x);
                d[1] = fmaf(-2.f, acc[nt][1], en.y);
                d[2] = fmaf(-2.f, acc[nt][2], en.x);
                d[3] = fmaf(-2.f, acc[nt][3], en.y);
                const int jj[4] = {j0, j0 + 1, j0, j0 + 1};
#pragma unroll
                for (int u = 0; u < 4; u++) {
                    const int q = u >> 1;            // row-slot
                    const float v = d[u];
                    if (v < t3v[q][2]) {
                        if (v < t3v[q][1]) {
                            t3v[q][2] = t3v[q][1]; t3i[q][2] = t3i[q][1];
                            if (v < t3v[q][0]) {
                                t3v[q][1] = t3v[q][0]; t3i[q][1] = t3i[q][0];
                                t3v[q][0] = v;         t3i[q][0] = jj[u];
                            } else {
                                t3v[q][1] = v; t3i[q][1] = jj[u];
                            }
                        } else {
                            t3v[q][2] = v; t3i[q][2] = jj[u];
                        }
                    }
                }
                acc[nt][0] = 0.f; acc[nt][1] = 0.f;
                acc[nt][2] = 0.f; acc[nt][3] = 0.f;
            }
        }
    }

    // ---- merge: dump per-(lane-group, n-half) top-3, pick top-6 ------------
    __syncthreads();              // all mma/ldmatrix smem reads done
    float* sV = (float*)smem;                 // [64 rows][8 src][3]
    int*   sI = (int*)(smem + 64 * 8 * 3 * 4);
    const int src = (wid >> 2) * 4 + (lane & 3);
#pragma unroll
    for (int q = 0; q < 2; q++) {
        const int row = mwarp + q * 8 + (lane >> 2);
        const int base = (row * 8 + src) * 3;
#pragma unroll
        for (int e = 0; e < 3; e++) {
            sV[base + e] = t3v[q][e];
            sI[base + e] = t3i[q][e];
        }
    }
    __syncthreads();
    if (t < MTILE) {
        float v6[NCAND];
        int   i6[NCAND];
#pragma unroll
        for (int c = 0; c < NCAND; c++) { v6[c] = 3.4e38f; i6[c] = c; }
        const int base = t * 24;
        for (int e = 0; e < 24; e++) {
            float v = sV[base + e];
            int   id = sI[base + e];
            if (v < v6[NCAND - 1]) {
                int p = NCAND - 1;
                while (p > 0 && v < v6[p - 1]) {
                    v6[p] = v6[p - 1]; i6[p] = i6[p - 1]; p--;
                }
                v6[p] = v; i6[p] = id;
            }
        }
        const int n = n0 + t;
#pragma unroll
        for (int c = 0; c < NCAND; c++) g_cand[n * NCAND + c] = i6[c];
    }
}

// ===========================================================================
// Prep kernels
// ===========================================================================
__global__ void enorm_kernel(const float* __restrict__ embed) {
    int j = blockIdx.x * blockDim.x + threadIdx.x;
    float s = 0.f;
#pragma unroll 8
    for (int d = 0; d < DIM; d++) {
        float v = embed[d * NCODE + j];
        s += v * v;
    }
    g_enorm[j] = s;
}

__global__ void transpose_split_kernel(const float* __restrict__ embed) {
    __shared__ float tile[32][33];
    int j0 = blockIdx.x * 32;
    int d0 = blockIdx.y * 32;
    int tx = threadIdx.x, ty = threadIdx.y;  // 32 x 8
#pragma unroll
    for (int i = 0; i < 4; i++)
        tile[ty + i * 8][tx] = embed[(size_t)(d0 + ty + i * 8) * NCODE + j0 + tx];
    __syncthreads();
#pragma unroll
    for (int i = 0; i < 4; i++) {
        float v = tile[tx][ty + i * 8];
        size_t o = (size_t)(j0 + ty + i * 8) * DIM + d0 + tx;
        g_embedT[o] = v;
        g_Bh[o] = __float2half_rn(v);
    }
}

// ===========================================================================
// Exact rescore (sequential k-order fp32 — validated rounding order) over 6
// candidates + gather + diff. One warp per row, 4 warps per block.
// ===========================================================================
__global__ __launch_bounds__(128)
void rescore_gather_kernel(const float* __restrict__ input,
                           float* __restrict__ out) {
    __shared__ float xs[4][256];
    __shared__ float es[4][NCAND][257];
    __shared__ double ws[4];

    const int wid = threadIdx.x >> 5, lane = threadIdx.x & 31;
    const int n = blockIdx.x * 4 + wid;

    int cand[NCAND];
#pragma unroll
    for (int c = 0; c < NCAND; c++) cand[c] = g_cand[n * NCAND + c];

    const float4* x4 = (const float4*)(input + (size_t)n * DIM);
    float4 v0 = x4[lane], v1 = x4[lane + 32];
    *(float4*)&xs[wid][lane * 4]       = v0;
    *(float4*)&xs[wid][128 + lane * 4] = v1;
#pragma unroll
    for (int c = 0; c < NCAND; c++) {
        const float4* e4 = (const float4*)(g_embedT + (size_t)cand[c] * DIM);
        float4 a = e4[lane], b = e4[lane + 32];
        es[wid][c][lane * 4 + 0] = a.x; es[wid][c][lane * 4 + 1] = a.y;
        es[wid][c][lane * 4 + 2] = a.z; es[wid][c][lane * 4 + 3] = a.w;
        es[wid][c][128 + lane * 4 + 0] = b.x; es[wid][c][128 + lane * 4 + 1] = b.y;
        es[wid][c][128 + lane * 4 + 2] = b.z; es[wid][c][128 + lane * 4 + 3] = b.w;
    }
    __syncwarp();

    float dist = 3.4e38f;
    int   cidx = 0x7fffffff;
    if (lane < NCAND) {
        float dot = 0.f;
#pragma unroll 8
        for (int k = 0; k < 256; k++)
            dot += xs[wid][k] * es[wid][lane][k];
        float en = __ldg(&g_enorm[cand[lane]]);
        dist = en - 2.0f * dot;
        cidx = cand[lane];
    }
    float bv = dist; int bi = cidx; int bslot = lane;
#pragma unroll
    for (int l = 0; l < NCAND; l++) {
        float ov = __shfl_sync(0xffffffffu, dist, l);
        int   oi = __shfl_sync(0xffffffffu, cidx, l);
        if (ov < bv || (ov == bv && oi < bi)) { bv = ov; bi = oi; bslot = l; }
    }
    const int w    = __shfl_sync(0xffffffffu, bslot, 0);
    const int widx = __shfl_sync(0xffffffffu, bi, 0);

    float4 oa, ob;
    oa.x = es[wid][w][lane * 4 + 0]; oa.y = es[wid][w][lane * 4 + 1];
    oa.z = es[wid][w][lane * 4 + 2]; oa.w = es[wid][w][lane * 4 + 3];
    ob.x = es[wid][w][128 + lane * 4 + 0]; ob.y = es[wid][w][128 + lane * 4 + 1];
    ob.z = es[wid][w][128 + lane * 4 + 2]; ob.w = es[wid][w][128 + lane * 4 + 3];

    float4* o4 = (float4*)(out + (size_t)n * DIM);
    o4[lane]      = oa;
    o4[lane + 32] = ob;
    if (lane == 0)
        out[IND_OFF + n] = (float)widx;

    float dx0 = oa.x - v0.x, dx1 = oa.y - v0.y, dx2 = oa.z - v0.z, dx3 = oa.w - v0.w;
    float dy0 = ob.x - v1.x, dy1 = ob.y - v1.y, dy2 = ob.z - v1.z, dy3 = ob.w - v1.w;
    float s = dx0 * dx0 + dx1 * dx1 + dx2 * dx2 + dx3 * dx3
            + dy0 * dy0 + dy1 * dy1 + dy2 * dy2 + dy3 * dy3;
    double sd = (double)s;
#pragma unroll
    for (int off = 16; off; off >>= 1)
        sd += __shfl_xor_sync(0xffffffffu, sd, off);
    if (lane == 0) ws[wid] = sd;
    __syncthreads();
    if (threadIdx.x == 0) {
        double tot = 0.0;
#pragma unroll
        for (int i = 0; i < 4; i++) tot += ws[i];
        g_part[blockIdx.x] = tot;
    }
}

__global__ void diff_kernel(float* __restrict__ out) {
    __shared__ double s[128];
    int t = threadIdx.x;
    double a = 0.0;
    for (int i = 0; i < 64; i++) a += g_part[t + i * 128];
    s[t] = a;
    __syncthreads();
    if (t == 0) {
        double tot = 0.0;
        for (int i = 0; i < 128; i++) tot += s[i];
        out[DIFF_OFF] = (float)(tot / (double)Q_ELEMS);
    }
}

// ===========================================================================
extern "C" void kernel_launch(void* const* d_in, const int* in_sizes, int n_in,
                              void* d_out, int out_size) {
    const float* input = (const float*)d_in[0];   // [8,64,64,256]
    const float* embed = (const float*)d_in[1];   // [256,4096]
    float* out = (float*)d_out;

    enorm_kernel<<<NCODE / 256, 256>>>(embed);
    transpose_split_kernel<<<dim3(NCODE / 32, DIM / 32), dim3(32, 8)>>>(embed);

    cudaFuncSetAttribute(vq_mma_kernel,
                         cudaFuncAttributeMaxDynamicSharedMemorySize, SMEM_TOT);
    vq_mma_kernel<<<NVEC / MTILE, 256, SMEM_TOT>>>(input);

    rescore_gather_kernel<<<NVEC / 4, 128>>>(input, out);
    diff_kernel<<<1, 128>>>(out);
}

// round 8
// speedup vs baseline: 4.5636x; 1.2243x over previous
#include <cuda_runtime.h>
#include <cuda_fp16.h>
#include <cstdint>

// Problem constants
#define NVEC   32768
#define DIM    256
#define NCODE  4096

// Output layout (all fp32): [quantize 8388608][diff 1][ind 32768]
#define Q_ELEMS   (NVEC * DIM)
#define DIFF_OFF  Q_ELEMS
#define IND_OFF   (Q_ELEMS + 1)

#define NCAND  8
#define MTILE  64

// Scratch
__device__ float  g_embedT[NCODE * DIM];            // [code][dim] fp32
__device__ __align__(16) __half g_Bh[NCODE * DIM];  // [code][dim] fp16 codes
__device__ float  g_enorm[NCODE];
__device__ int    g_cand[NVEC * NCAND];
__device__ double g_part[8192];

// ---------------------------------------------------------------------------
__device__ __forceinline__ uint32_t smem_u32(const void* p) {
    uint32_t a;
    asm("{ .reg .u64 t; cvta.to.shared.u64 t, %1; cvt.u32.u64 %0, t; }"
        : "=r"(a) : "l"(p));
    return a;
}
__device__ __forceinline__ void ldsm_x4(uint32_t r[4], uint32_t addr) {
    asm volatile("ldmatrix.sync.aligned.m8n8.x4.shared.b16 {%0,%1,%2,%3}, [%4];"
                 : "=r"(r[0]), "=r"(r[1]), "=r"(r[2]), "=r"(r[3]) : "r"(addr));
}
__device__ __forceinline__ void mma_f16(float c[4], const uint32_t a[4],
                                        const uint32_t b0, const uint32_t b1) {
    asm volatile(
        "mma.sync.aligned.m16n8k16.row.col.f32.f16.f16.f32 "
        "{%0,%1,%2,%3}, {%4,%5,%6,%7}, {%8,%9}, {%0,%1,%2,%3};"
        : "+f"(c[0]), "+f"(c[1]), "+f"(c[2]), "+f"(c[3])
        : "r"(a[0]), "r"(a[1]), "r"(a[2]), "r"(a[3]), "r"(b0), "r"(b1));
}
#define CP_ASYNC16(dst, src) \
    asm volatile("cp.async.cg.shared.global [%0], [%1], 16;" \
                 :: "r"(dst), "l"(src) : "memory")
#define CP_COMMIT()  asm volatile("cp.async.commit_group;" ::: "memory")
#define CP_WAIT2()   asm volatile("cp.async.wait_group 2;" ::: "memory")

// ---------------------------------------------------------------------------
// SMEM: A resident (64 x 264 halves, 528B rows, fp16 only); B: 4 bufs of
// 128 codes x 32 k fp16 (80B rows).
#define A_ROW_B   528
#define A_BYTES   33792            // 64*528
#define B_BASE    33792
#define B_ROW_B   80
#define B_BUF_B   10240            // 128*80
#define SMEM_TOT  (B_BASE + 4 * B_BUF_B)   // 74752 -> 2 CTAs/SM

// ===========================================================================
// Single-product fp16 mma GEMM + per-thread top-3 + merged top-8.
// Grid 512 (64 rows/CTA), block 256 (8 warps: 4m x 2n, warp tile 16x64).
// ===========================================================================
__global__ __launch_bounds__(256, 2)
void vq_mma_kernel(const float* __restrict__ x) {
    extern __shared__ char smem[];
    const uint32_t sb = smem_u32(smem);
    const int t    = threadIdx.x;
    const int wid  = t >> 5, lane = t & 31;
    const int n0   = blockIdx.x * MTILE;
    const int mwarp = (wid & 3) * 16;
    const int nwarp = (wid >> 2) * 64;

    // ---- convert A (64 x rows) to fp16 in smem ----------------------------
    {
        const float4* xg4 = (const float4*)(x + (size_t)n0 * DIM);
#pragma unroll
        for (int i = 0; i < 16; i++) {
            const int f   = t + i * 256;          // 0..4095 float4
            const int row = f >> 6;
            const int c4  = f & 63;
            float4 v = xg4[f];
            __half hx = __float2half_rn(v.x), hy = __float2half_rn(v.y);
            __half hz = __float2half_rn(v.z), hw = __float2half_rn(v.w);
            const int off = row * A_ROW_B + c4 * 8;
            *(__half2*)(smem + off)     = __halves2half2(hx, hy);
            *(__half2*)(smem + off + 4) = __halves2half2(hz, hw);
        }
    }

    const uint32_t aBase = sb + (uint32_t)(mwarp + (lane & 15)) * A_ROW_B
                         + (uint32_t)(((lane >> 4) & 1) * 8) * 2;
    const uint32_t bBase = sb + B_BASE
                         + (uint32_t)(nwarp + (lane & 7) + ((lane >> 4) & 1) * 8) * B_ROW_B
                         + (uint32_t)(((lane >> 3) & 1) * 8) * 2;

    // B chunk (128 codes x 32 k fp16, 8KB): 512 x 16B
    auto issueB = [&](int ch) {
        const int nb = (ch >> 3) * 128;
        const int kb = (ch & 7) * 32;
        const uint32_t bufb = sb + B_BASE + (uint32_t)(ch & 3) * B_BUF_B;
#pragma unroll
        for (int j = 0; j < 2; j++) {
            const int s = t + j * 256;           // 0..511
            const int r = s >> 2;
            const int q = s & 3;
            const uint32_t dst = bufb + (uint32_t)r * B_ROW_B + (uint32_t)q * 16;
            const __half* srcp = g_Bh + (size_t)(nb + r) * DIM + kb + q * 8;
            CP_ASYNC16(dst, srcp);
        }
    };

    float acc[8][4];
#pragma unroll
    for (int nt = 0; nt < 8; nt++)
#pragma unroll
        for (int q = 0; q < 4; q++) acc[nt][q] = 0.f;

    // per-thread top-3 per row-slot (2 slots: rows lane>>2 and +8)
    float t3v[2][3];
    int   t3i[2][3];
#pragma unroll
    for (int q = 0; q < 2; q++) {
        t3v[q][0] = 3.4e38f; t3v[q][1] = 3.4e38f; t3v[q][2] = 3.4e38f;
        t3i[q][0] = 0; t3i[q][1] = 1; t3i[q][2] = 2;
    }

    issueB(0); CP_COMMIT();
    issueB(1); CP_COMMIT();
    issueB(2); CP_COMMIT();

    const float2* en2 = (const float2*)g_enorm;

    for (int i = 0; i < 256; i++) {
        CP_WAIT2();
        __syncthreads();

        if (i + 3 < 256) issueB(i + 3);
        CP_COMMIT();

        const uint32_t bufb = (uint32_t)(i & 3) * B_BUF_B;
        const uint32_t kcb  = (uint32_t)(i & 7) * 32;

#pragma unroll
        for (int kk = 0; kk < 2; kk++) {
            const uint32_t kab = (kcb + kk * 16) * 2;
            uint32_t ah[4];
            ldsm_x4(ah, aBase + kab);
            uint32_t bh[8][2];
#pragma unroll
            for (int np = 0; np < 4; np++) {
                uint32_t r[4];
                ldsm_x4(r, bBase + bufb + (uint32_t)np * (16 * B_ROW_B) + (uint32_t)kk * 32);
                bh[np * 2][0] = r[0]; bh[np * 2][1] = r[1];
                bh[np * 2 + 1][0] = r[2]; bh[np * 2 + 1][1] = r[3];
            }
#pragma unroll
            for (int nt = 0; nt < 8; nt++)
                mma_f16(acc[nt], ah, bh[nt][0], bh[nt][1]);
        }

        if ((i & 7) == 7) {
            const int cbase = (i >> 3) * 128;
#pragma unroll
            for (int nt = 0; nt < 8; nt++) {
                const int j0 = cbase + nwarp + nt * 8 + (lane & 3) * 2;
                const float2 en = __ldg(&en2[j0 >> 1]);
                float d[4];
                d[0] = fmaf(-2.f, acc[nt][0], en.x);
                d[1] = fmaf(-2.f, acc[nt][1], en.y);
                d[2] = fmaf(-2.f, acc[nt][2], en.x);
                d[3] = fmaf(-2.f, acc[nt][3], en.y);
                const int jj[4] = {j0, j0 + 1, j0, j0 + 1};
#pragma unroll
                for (int u = 0; u < 4; u++) {
                    const int q = u >> 1;            // row-slot
                    const float v = d[u];
                    if (v < t3v[q][2]) {
                        if (v < t3v[q][1]) {
                            t3v[q][2] = t3v[q][1]; t3i[q][2] = t3i[q][1];
                            if (v < t3v[q][0]) {
                                t3v[q][1] = t3v[q][0]; t3i[q][1] = t3i[q][0];
                                t3v[q][0] = v;         t3i[q][0] = jj[u];
                            } else {
                                t3v[q][1] = v; t3i[q][1] = jj[u];
                            }
                        } else {
                            t3v[q][2] = v; t3i[q][2] = jj[u];
                        }
                    }
                }
                acc[nt][0] = 0.f; acc[nt][1] = 0.f;
                acc[nt][2] = 0.f; acc[nt][3] = 0.f;
            }
        }
    }

    // ---- merge: dump per-(lane-group, n-half) top-3, pick top-8 ------------
    __syncthreads();              // all mma/ldmatrix smem reads done
    float* sV = (float*)smem;                 // [64 rows][8 src][3]
    int*   sI = (int*)(smem + 64 * 8 * 3 * 4);
    const int src = (wid >> 2) * 4 + (lane & 3);
#pragma unroll
    for (int q = 0; q < 2; q++) {
        const int row = mwarp + q * 8 + (lane >> 2);
        const int base = (row * 8 + src) * 3;
#pragma unroll
        for (int e = 0; e < 3; e++) {
            sV[base + e] = t3v[q][e];
            sI[base + e] = t3i[q][e];
        }
    }
    __syncthreads();
    if (t < MTILE) {
        float v8[NCAND];
        int   i8[NCAND];
#pragma unroll
        for (int c = 0; c < NCAND; c++) { v8[c] = 3.4e38f; i8[c] = c; }
        const int base = t * 24;
        for (int e = 0; e < 24; e++) {
            float v = sV[base + e];
            int   id = sI[base + e];
            if (v < v8[NCAND - 1]) {
                int p = NCAND - 1;
                while (p > 0 && v < v8[p - 1]) {
                    v8[p] = v8[p - 1]; i8[p] = i8[p - 1]; p--;
                }
                v8[p] = v; i8[p] = id;
            }
        }
        const int n = n0 + t;
#pragma unroll
        for (int c = 0; c < NCAND; c++) g_cand[n * NCAND + c] = i8[c];
    }
}

// ===========================================================================
// Prep kernels
// ===========================================================================
__global__ void enorm_kernel(const float* __restrict__ embed) {
    int j = blockIdx.x * blockDim.x + threadIdx.x;
    float s = 0.f;
#pragma unroll 8
    for (int d = 0; d < DIM; d++) {
        float v = embed[d * NCODE + j];
        s += v * v;
    }
    g_enorm[j] = s;
}

__global__ void transpose_split_kernel(const float* __restrict__ embed) {
    __shared__ float tile[32][33];
    int j0 = blockIdx.x * 32;
    int d0 = blockIdx.y * 32;
    int tx = threadIdx.x, ty = threadIdx.y;  // 32 x 8
#pragma unroll
    for (int i = 0; i < 4; i++)
        tile[ty + i * 8][tx] = embed[(size_t)(d0 + ty + i * 8) * NCODE + j0 + tx];
    __syncthreads();
#pragma unroll
    for (int i = 0; i < 4; i++) {
        float v = tile[tx][ty + i * 8];
        size_t o = (size_t)(j0 + ty + i * 8) * DIM + d0 + tx;
        g_embedT[o] = v;
        g_Bh[o] = __float2half_rn(v);
    }
}

// ===========================================================================
// Exact rescore (sequential k-order fp32 — validated rounding order) over 8
// candidates + gather + diff. One warp per row, 4 warps per block.
// ===========================================================================
__global__ __launch_bounds__(128)
void rescore_gather_kernel(const float* __restrict__ input,
                           float* __restrict__ out) {
    __shared__ float xs[4][256];
    __shared__ float es[4][NCAND][257];
    __shared__ double ws[4];

    const int wid = threadIdx.x >> 5, lane = threadIdx.x & 31;
    const int n = blockIdx.x * 4 + wid;

    int cand[NCAND];
#pragma unroll
    for (int c = 0; c < NCAND; c++) cand[c] = g_cand[n * NCAND + c];

    const float4* x4 = (const float4*)(input + (size_t)n * DIM);
    float4 v0 = x4[lane], v1 = x4[lane + 32];
    *(float4*)&xs[wid][lane * 4]       = v0;
    *(float4*)&xs[wid][128 + lane * 4] = v1;
#pragma unroll
    for (int c = 0; c < NCAND; c++) {
        const float4* e4 = (const float4*)(g_embedT + (size_t)cand[c] * DIM);
        float4 a = e4[lane], b = e4[lane + 32];
        es[wid][c][lane * 4 + 0] = a.x; es[wid][c][lane * 4 + 1] = a.y;
        es[wid][c][lane * 4 + 2] = a.z; es[wid][c][lane * 4 + 3] = a.w;
        es[wid][c][128 + lane * 4 + 0] = b.x; es[wid][c][128 + lane * 4 + 1] = b.y;
        es[wid][c][128 + lane * 4 + 2] = b.z; es[wid][c][128 + lane * 4 + 3] = b.w;
    }
    __syncwarp();

    float dist = 3.4e38f;
    int   cidx = 0x7fffffff;
    if (lane < NCAND) {
        float dot = 0.f;
#pragma unroll 8
        for (int k = 0; k < 256; k++)
            dot += xs[wid][k] * es[wid][lane][k];
        float en = __ldg(&g_enorm[cand[lane]]);
        dist = en - 2.0f * dot;
        cidx = cand[lane];
    }
    float bv = dist; int bi = cidx; int bslot = lane;
#pragma unroll
    for (int l = 0; l < NCAND; l++) {
        float ov = __shfl_sync(0xffffffffu, dist, l);
        int   oi = __shfl_sync(0xffffffffu, cidx, l);
        if (ov < bv || (ov == bv && oi < bi)) { bv = ov; bi = oi; bslot = l; }
    }
    const int w    = __shfl_sync(0xffffffffu, bslot, 0);
    const int widx = __shfl_sync(0xffffffffu, bi, 0);

    float4 oa, ob;
    oa.x = es[wid][w][lane * 4 + 0]; oa.y = es[wid][w][lane * 4 + 1];
    oa.z = es[wid][w][lane * 4 + 2]; oa.w = es[wid][w][lane * 4 + 3];
    ob.x = es[wid][w][128 + lane * 4 + 0]; ob.y = es[wid][w][128 + lane * 4 + 1];
    ob.z = es[wid][w][128 + lane * 4 + 2]; ob.w = es[wid][w][128 + lane * 4 + 3];

    float4* o4 = (float4*)(out + (size_t)n * DIM);
    o4[lane]      = oa;
    o4[lane + 32] = ob;
    if (lane == 0)
        out[IND_OFF + n] = (float)widx;

    float dx0 = oa.x - v0.x, dx1 = oa.y - v0.y, dx2 = oa.z - v0.z, dx3 = oa.w - v0.w;
    float dy0 = ob.x - v1.x, dy1 = ob.y - v1.y, dy2 = ob.z - v1.z, dy3 = ob.w - v1.w;
    float s = dx0 * dx0 + dx1 * dx1 + dx2 * dx2 + dx3 * dx3
            + dy0 * dy0 + dy1 * dy1 + dy2 * dy2 + dy3 * dy3;
    double sd = (double)s;
#pragma unroll
    for (int off = 16; off; off >>= 1)
        sd += __shfl_xor_sync(0xffffffffu, sd, off);
    if (lane == 0) ws[wid] = sd;
    __syncthreads();
    if (threadIdx.x == 0) {
        double tot = 0.0;
#pragma unroll
        for (int i = 0; i < 4; i++) tot += ws[i];
        g_part[blockIdx.x] = tot;
    }
}

__global__ void diff_kernel(float* __restrict__ out) {
    __shared__ double s[128];
    int t = threadIdx.x;
    double a = 0.0;
    for (int i = 0; i < 64; i++) a += g_part[t + i * 128];
    s[t] = a;
    __syncthreads();
    if (t == 0) {
        double tot = 0.0;
        for (int i = 0; i < 128; i++) tot += s[i];
        out[DIFF_OFF] = (float)(tot / (double)Q_ELEMS);
    }
}

// ===========================================================================
extern "C" void kernel_launch(void* const* d_in, const int* in_sizes, int n_in,
                              void* d_out, int out_size) {
    const float* input = (const float*)d_in[0];   // [8,64,64,256]
    const float* embed = (const float*)d_in[1];   // [256,4096]
    float* out = (float*)d_out;

    enorm_kernel<<<NCODE / 256, 256>>>(embed);
    transpose_split_kernel<<<dim3(NCODE / 32, DIM / 32), dim3(32, 8)>>>(embed);

    cudaFuncSetAttribute(vq_mma_kernel,
                         cudaFuncAttributeMaxDynamicSharedMemorySize, SMEM_TOT);
    vq_mma_kernel<<<NVEC / MTILE, 256, SMEM_TOT>>>(input);

    rescore_gather_kernel<<<NVEC / 4, 128>>>(input, out);
    diff_kernel<<<1, 128>>>(out);
}